// round 14
// baseline (speedup 1.0000x reference)
#include <cuda_runtime.h>
#include <cuda_fp16.h>
#include <mma.h>
#include <cstdint>

using namespace nvcuda;

#define TSTEPS 512
#define BATCH  128
#define HID    1024
#define NG     4096
#define NLAYER 2
#define NCTA_R 128
#define THR_TOT 320   // 8 consumer warps + 2 producer warps
#define N_CONS  256

// ---------------- device scratch ----------------
__device__ float  g_gatesT[(size_t)TSTEPS * NG * BATCH];          // [t][col][b]
__device__ __align__(16) __half g_hseq16[(size_t)TSTEPS * BATCH * HID];
__device__ __align__(16) __half g_h16[2][BATCH * HID];            // ping-pong h
__device__ __align__(16) __half g_x16[(size_t)TSTEPS * BATCH * HID];   // fp16 x
__device__ __align__(16) __half g_w16[(size_t)NLAYER * HID * NG];      // fp16 W_ih
__device__ unsigned int g_full[16];   // [bg][chunk]: 8 consumer arrivals per step
__device__ unsigned int g_cons[2];    // [bg]: 64 producer arrivals per step

// ---------------- recurrence smem layout (bytes) ----------------
#define SM_W     0
#define SM_A     147456
#define SM_ABUF  17408
#define SM_G     182272
#define SM_BIAS  217088
#define SM_TOTAL 217344

// ---------------- input-GEMM smem layout (bytes) ----------------
#define GI_A      0
#define GI_ABUF   10240
#define GI_B      30720
#define GI_BBUF   16896
#define GI_TOTAL  81408

__device__ __forceinline__ uint32_t smem_u32(const void* p) {
    uint32_t a;
    asm("{ .reg .u64 t; cvta.to.shared.u64 t, %1; cvt.u32.u64 %0, t; }" : "=r"(a) : "l"(p));
    return a;
}
__device__ __forceinline__ void cp16(uint32_t dst, const void* src) {
    asm volatile("cp.async.cg.shared.global [%0], [%1], 16;" :: "r"(dst), "l"(src));
}
#define CP_COMMIT() asm volatile("cp.async.commit_group;" ::: "memory")
#define CP_WAIT1()  asm volatile("cp.async.wait_group 1;" ::: "memory")
#define CP_WAIT0()  asm volatile("cp.async.wait_group 0;" ::: "memory")

#define BAR_SYNC(id, n)   asm volatile("bar.sync %0, %1;"   :: "r"(id), "r"(n) : "memory")
#define BAR_ARRIVE(id, n) asm volatile("bar.arrive %0, %1;" :: "r"(id), "r"(n) : "memory")

__device__ __forceinline__ void rel_add1(unsigned int* p) {
    asm volatile("red.release.gpu.global.add.u32 [%0], 1;" :: "l"(p) : "memory");
}
__device__ __forceinline__ unsigned int acq_ld(const unsigned int* p) {
    unsigned int v;
    asm volatile("ld.acquire.gpu.global.u32 %0, [%1];" : "=r"(v) : "l"(p) : "memory");
    return v;
}

__device__ __forceinline__ float sigf(float x) { return 1.f / (1.f + __expf(-x)); }
__device__ __forceinline__ uint32_t packh2(float a, float b) {
    return (uint32_t)__half_as_ushort(__float2half_rn(a)) |
           ((uint32_t)__half_as_ushort(__float2half_rn(b)) << 16);
}

// =================================================================================
// fp32 -> fp16 conversion (x and W_ih, once)
// =================================================================================
__global__ void cvt_f32_f16(const float* __restrict__ src, __half* __restrict__ dst)
{
    const size_t i = ((size_t)blockIdx.x * blockDim.x + threadIdx.x) * 4;
    const float4 v = *(const float4*)(src + i);
    *(uint2*)(dst + i) = make_uint2(packh2(v.x, v.y), packh2(v.z, v.w));
}

// =================================================================================
// Input GEMM fp16 (unchanged from round 13)
// =================================================================================
__global__ void __launch_bounds__(256, 1) gemm_input_f16(
    const __half* __restrict__ A,      // [T*B, 1024] fp16
    const __half* __restrict__ W,      // [1024, 4096] fp16
    float* __restrict__ CT)            // [T][col][b]
{
    extern __shared__ __align__(16) char smem[];
    const uint32_t sbase = smem_u32(smem);

    const int tid  = threadIdx.x;
    const int warp = tid >> 5;
    const int wm = warp >> 2;
    const int wn = warp & 3;
    const int bm = blockIdx.y;
    const int bn = blockIdx.x;

    const int a_row = tid >> 1, a_c8 = (tid & 1) * 16;
    const int b_row = tid >> 3, b_c8 = (tid & 7) * 32;

    const __half* Ag = A + (size_t)(bm * 128 + a_row) * HID;
    const __half* Wg = W + (size_t)b_row * NG + bn * 256;

    wmma::fragment<wmma::accumulator, 16, 16, 16, float> acc[4][4];
#pragma unroll
    for (int i = 0; i < 4; i++)
#pragma unroll
        for (int j = 0; j < 4; j++) wmma::fill_fragment(acc[i][j], 0.f);

#pragma unroll
    for (int c = 0; c < 2; ++c) {
        const uint32_t abase = sbase + GI_A + c * GI_ABUF;
        const uint32_t bbase = sbase + GI_B + c * GI_BBUF;
#pragma unroll
        for (int u = 0; u < 2; u++)
            cp16(abase + (uint32_t)(a_row * 40 + a_c8 + u * 8) * 2,
                 Ag + c * 32 + a_c8 + u * 8);
#pragma unroll
        for (int u = 0; u < 4; u++)
            cp16(bbase + (uint32_t)(b_row * 264 + b_c8 + u * 8) * 2,
                 Wg + (size_t)(c * 32) * NG + b_c8 + u * 8);
        CP_COMMIT();
    }

#pragma unroll 1
    for (int cc = 0; cc < 32; ++cc) {
        if (cc < 31) CP_WAIT1(); else CP_WAIT0();
        __syncthreads();

        if (cc < 30) {
            const int cn = cc + 2;
            const uint32_t abase = sbase + GI_A + (cn % 3) * GI_ABUF;
            const uint32_t bbase = sbase + GI_B + (cn % 3) * GI_BBUF;
#pragma unroll
            for (int u = 0; u < 2; u++)
                cp16(abase + (uint32_t)(a_row * 40 + a_c8 + u * 8) * 2,
                     Ag + cn * 32 + a_c8 + u * 8);
#pragma unroll
            for (int u = 0; u < 4; u++)
                cp16(bbase + (uint32_t)(b_row * 264 + b_c8 + u * 8) * 2,
                     Wg + (size_t)(cn * 32) * NG + b_c8 + u * 8);
            CP_COMMIT();
        }

        const __half* As = (const __half*)(smem + GI_A + (cc % 3) * GI_ABUF);
        const __half* Bs = (const __half*)(smem + GI_B + (cc % 3) * GI_BBUF);
#pragma unroll
        for (int kk = 0; kk < 32; kk += 16) {
            wmma::fragment<wmma::matrix_a, 16, 16, 16, __half, wmma::row_major> fa[4];
            wmma::fragment<wmma::matrix_b, 16, 16, 16, __half, wmma::row_major> fb[4];
#pragma unroll
            for (int i = 0; i < 4; i++)
                wmma::load_matrix_sync(fa[i], As + (size_t)(wm * 64 + i * 16) * 40 + kk, 40);
#pragma unroll
            for (int j = 0; j < 4; j++)
                wmma::load_matrix_sync(fb[j], Bs + (size_t)kk * 264 + wn * 64 + j * 16, 264);
#pragma unroll
            for (int i = 0; i < 4; i++)
#pragma unroll
                for (int j = 0; j < 4; j++)
                    wmma::mma_sync(acc[i][j], fa[i], fb[j], acc[i][j]);
        }
    }

    float* base = CT + (size_t)bm * NG * 128;
#pragma unroll
    for (int i = 0; i < 4; i++)
#pragma unroll
        for (int j = 0; j < 4; j++) {
            const int col = bn * 256 + wn * 64 + j * 16;
            const int row = wm * 64 + i * 16;
            wmma::store_matrix_sync(base + (size_t)col * 128 + row, acc[i][j],
                                    128, wmma::mem_col_major);
        }
}

// =================================================================================
__global__ void lstm_init()
{
    const int i = blockIdx.x * blockDim.x + threadIdx.x;   // 65536
    if (i < 16) g_full[i] = 0u;
    if (i < 2)  g_cons[i] = 0u;
    ((uint32_t*)g_h16[0])[i] = 0u;
}

// =================================================================================
// Persistent recurrence: batch-split + warp-specialized + PER-CHUNK DATAFLOW SYNC.
// No global barrier. Producers poll g_full[bg][c] (8 writer-CTA arrivals per step)
// before staging chunk c; consumers poll g_cons[bg] (64 producer arrivals, one
// step of slack) before overwriting the ping-pong h buffer. All dependency
// chains go backward in (t, chunk) -> deadlock-free, steps pipeline across CTAs.
// =================================================================================
__global__ void __launch_bounds__(THR_TOT, 1) lstm_recur(
    const float* __restrict__ Whh,      // [HID, NG]
    const float* __restrict__ gatesT,   // [T][col][b]
    const float* __restrict__ b1, const float* __restrict__ b2,
    __half* __restrict__ seq16,         // layer-0 output (or null)
    float*  __restrict__ seq32,         // last-layer output (or null)
    float* __restrict__ hT, float* __restrict__ cT)
{
    extern __shared__ __align__(16) char smem[];
    __half* Ws   = (__half*)(smem + SM_W);       // [1024][72]
    float*  Gs0  = (float*) (smem + SM_G);       // [64][68]
    float*  Gs1  = Gs0 + 64 * 68;
    float*  bias = (float*) (smem + SM_BIAS);    // [64]
    const uint32_t sbase = smem_u32(smem);

    const int tid = threadIdx.x;
    const int bx  = blockIdx.x;
    const int jg  = bx & 63;            // j-group: hidden cols [jg*16, jg*16+16)
    const int bg  = bx >> 6;            // batch group: rows [bg*64, bg*64+64)
    const int j0  = jg * 16;
    const int m0  = bg * 64;

    for (int idx = tid; idx < 1024 * 64; idx += THR_TOT) {
        const int k = idx >> 6, n = idx & 63;
        const int gate = n & 3, jl = n >> 2;
        Ws[k * 72 + n] = __float2half_rn(Whh[(size_t)k * NG + gate * HID + j0 + jl]);
    }
    if (tid < 64) {
        const int gate = tid & 3, jl = tid >> 2;
        bias[tid] = b1[gate * HID + j0 + jl] + b2[gate * HID + j0 + jl];
    }
    __syncthreads();

    if (tid >= N_CONS) {
        // =========================== PRODUCER WARPS ===========================
        const int ptid = tid - N_CONS;   // 0..63
        unsigned int* fullf = g_full + bg * 8;
#pragma unroll 1
        for (int t = 0; t < TSTEPS; ++t) {
            const __half* hin = g_h16[t & 1] + (size_t)m0 * HID;
#pragma unroll 1
            for (int cc = 0; cc < 8; ++cc) {
                const int g = t * 8 + cc;
                const int slot = cc & 1;
                if (g >= 2) BAR_SYNC(3 + slot, THR_TOT);    // wait slot empty
                if (t > 0) {                                 // wait writers of h_t chunk cc
                    const unsigned tgt = 8u * (unsigned)t;
                    while (acq_ld(&fullf[cc]) < tgt) { }
                }
                const uint32_t dbase = sbase + SM_A + slot * SM_ABUF;
                const __half* hp = hin + cc * 128;
#pragma unroll
                for (int u = 0; u < 16; u++) {
                    const int idx = u * 64 + ptid;
                    const int row = idx >> 4, k8 = (idx & 15) * 8;
                    cp16(dbase + (uint32_t)(row * 136 + k8) * 2,
                         hp + (size_t)row * HID + k8);
                }
                CP_COMMIT();
                if (cc >= 1) {
                    CP_WAIT1();
                    BAR_ARRIVE(1 + ((cc - 1) & 1), THR_TOT);
                }
            }
            CP_WAIT0();
            BAR_ARRIVE(2, THR_TOT);                         // FULL for chunk 7 (slot 1)
            BAR_SYNC(7, 64);                                // all producer reads done
            if (ptid == 0) rel_add1(&g_cons[bg]);           // h_t buffer fully consumed
        }
        return;
    }

    // ============================ CONSUMER WARPS ============================
    const int wid   = tid >> 5;
    const int mhalf = wid & 1;
    const int nposw = (wid >> 1) & 1;
    const int khalf = wid >> 2;

    const int m    = tid & 63;
    const int jgrp = tid >> 6;
    unsigned int* myfull = &g_full[bg * 8 + (jg >> 3)];
    float c4[4];
#pragma unroll
    for (int q = 0; q < 4; q++) c4[q] = 0.f;

    float gt[16];
    {
        const float* gb = gatesT + (m0 + m);
#pragma unroll
        for (int q = 0; q < 4; q++)
#pragma unroll
            for (int g = 0; g < 4; g++)
                gt[q * 4 + g] = gb[(size_t)(g * HID + j0 + jgrp * 4 + q) * BATCH];
    }

#pragma unroll 1
    for (int t = 0; t < TSTEPS; ++t) {
        __half* hout = g_h16[(t + 1) & 1];

        wmma::fragment<wmma::accumulator, 16, 16, 16, float> acc[2][2];
#pragma unroll
        for (int i = 0; i < 2; i++)
#pragma unroll
            for (int j = 0; j < 2; j++) wmma::fill_fragment(acc[i][j], 0.f);

#pragma unroll 1
        for (int cc = 0; cc < 8; ++cc) {
            const int slot = cc & 1;
            BAR_SYNC(1 + slot, THR_TOT);    // wait slot full

            const __half* Ap = (const __half*)(smem + SM_A + slot * SM_ABUF)
                             + (size_t)mhalf * 32 * 136 + khalf * 64;
            const __half* Wp = Ws + (size_t)(cc * 128 + khalf * 64) * 72 + nposw * 32;
#pragma unroll
            for (int kk = 0; kk < 64; kk += 16) {
                wmma::fragment<wmma::matrix_a, 16, 16, 16, __half, wmma::row_major> fa[2];
                wmma::fragment<wmma::matrix_b, 16, 16, 16, __half, wmma::row_major> fb[2];
#pragma unroll
                for (int i = 0; i < 2; i++)
                    wmma::load_matrix_sync(fa[i], Ap + (size_t)(i * 16) * 136 + kk, 136);
#pragma unroll
                for (int j = 0; j < 2; j++)
                    wmma::load_matrix_sync(fb[j], Wp + (size_t)kk * 72 + j * 16, 72);
#pragma unroll
                for (int i = 0; i < 2; i++)
#pragma unroll
                    for (int j = 0; j < 2; j++)
                        wmma::mma_sync(acc[i][j], fa[i], fb[j], acc[i][j]);
            }
            BAR_ARRIVE(3 + slot, THR_TOT);  // slot consumed
        }

        float* Gsw = khalf ? Gs1 : Gs0;
#pragma unroll
        for (int i = 0; i < 2; i++)
#pragma unroll
            for (int j = 0; j < 2; j++)
                wmma::store_matrix_sync(Gsw + (size_t)(mhalf * 32 + i * 16) * 68
                                             + nposw * 32 + j * 16,
                                        acc[i][j], 68, wmma::mem_row_major);
        BAR_SYNC(9, N_CONS);

        float hn[4];
#pragma unroll
        for (int q = 0; q < 4; q++) {
            const int n = jgrp * 16 + q * 4;
            const float4 v0 = *(const float4*)(Gs0 + (size_t)m * 68 + n);
            const float4 v1 = *(const float4*)(Gs1 + (size_t)m * 68 + n);
            const float zi = v0.x + v1.x + gt[q * 4 + 0] + bias[n + 0];
            const float zf = v0.y + v1.y + gt[q * 4 + 1] + bias[n + 1];
            const float zg = v0.z + v1.z + gt[q * 4 + 2] + bias[n + 2];
            const float zo = v0.w + v1.w + gt[q * 4 + 3] + bias[n + 3];
            const float cn = sigf(zf) * c4[q] + sigf(zi) * tanhf(zg);
            hn[q] = sigf(zo) * tanhf(cn);
            c4[q] = cn;
        }

        // WAR guard: h_{t+1} overwrites h_{t-1}; its readers (producers, step
        // t-1) must be done. One full step of slack -> wait almost always free.
        if (t > 0) {
            const unsigned tgt = 64u * (unsigned)t;
            while (acq_ld(&g_cons[bg]) < tgt) { }
        }

        const size_t ob = (size_t)(m0 + m) * HID + j0 + jgrp * 4;
        const uint2 upk = make_uint2(packh2(hn[0], hn[1]), packh2(hn[2], hn[3]));
        *(uint2*)(hout + ob) = upk;

        BAR_SYNC(9, N_CONS);               // all consumer hout stores done
        if (tid == 0) rel_add1(myfull);    // publish h_{t+1} chunk (jg>>3)

        // ---- work shadow ----
        if (seq16) *(uint2*)(seq16 + (size_t)t * BATCH * HID + ob) = upk;
        if (seq32)
            *(float4*)(seq32 + (size_t)t * BATCH * HID + ob) =
                make_float4(hn[0], hn[1], hn[2], hn[3]);
        if (t == TSTEPS - 1) {
            *(float4*)(hT + ob) = make_float4(hn[0], hn[1], hn[2], hn[3]);
            *(float4*)(cT + ob) = make_float4(c4[0], c4[1], c4[2], c4[3]);
        }
        if (t + 1 < TSTEPS) {
            const float* gb = gatesT + (size_t)(t + 1) * NG * BATCH + (m0 + m);
#pragma unroll
            for (int q = 0; q < 4; q++)
#pragma unroll
                for (int g = 0; g < 4; g++)
                    gt[q * 4 + g] = gb[(size_t)(g * HID + j0 + jgrp * 4 + q) * BATCH];
        }
    }
}

// =================================================================================
extern "C" void kernel_launch(void* const* d_in, const int* in_sizes, int n_in,
                              void* d_out, int out_size)
{
    const float* x   = (const float*)d_in[0];
    const float* wih = (const float*)d_in[1];
    const float* whh = (const float*)d_in[2];
    const float* bih = (const float*)d_in[3];
    const float* bhh = (const float*)d_in[4];
    float* out = (float*)d_out;

    cudaFuncSetAttribute(lstm_recur, cudaFuncAttributeMaxDynamicSharedMemorySize, SM_TOTAL);
    cudaFuncSetAttribute(gemm_input_f16, cudaFuncAttributeMaxDynamicSharedMemorySize, GI_TOTAL);

    float  *gatesT;
    __half *hseq16, *x16, *w16;
    cudaGetSymbolAddress((void**)&gatesT, g_gatesT);
    cudaGetSymbolAddress((void**)&hseq16, g_hseq16);
    cudaGetSymbolAddress((void**)&x16,    g_x16);
    cudaGetSymbolAddress((void**)&w16,    g_w16);

    float* hT_base = out + (size_t)TSTEPS * BATCH * HID;
    float* cT_base = hT_base + (size_t)NLAYER * BATCH * HID;

    cvt_f32_f16<<<(TSTEPS * BATCH * HID) / 1024, 256>>>(x, x16);
    cvt_f32_f16<<<(NLAYER * HID * NG) / 1024, 256>>>(wih, w16);

    for (int l = 0; l < NLAYER; ++l) {
        const __half* A16 = l ? hseq16 : x16;
        const __half* W16 = w16 + (size_t)l * HID * NG;
        const float* Whh = whh + (size_t)l * HID * NG;
        const float* B1  = bih + (size_t)l * NG;
        const float* B2  = bhh + (size_t)l * NG;
        float* hT = hT_base + (size_t)l * BATCH * HID;
        float* cT = cT_base + (size_t)l * BATCH * HID;

        gemm_input_f16<<<dim3(NG / 256, TSTEPS), 256, GI_TOTAL>>>(A16, W16, gatesT);

        lstm_init<<<256, 256>>>();

        lstm_recur<<<NCTA_R, THR_TOT, SM_TOTAL>>>(
            Whh, gatesT, B1, B2,
            (l == 0) ? hseq16 : (__half*)nullptr,
            (l == 1) ? out    : (float*)nullptr,
            hT, cT);
    }
}

// round 15
// speedup vs baseline: 1.1064x; 1.1064x over previous
#include <cuda_runtime.h>
#include <cuda_fp16.h>
#include <mma.h>
#include <cstdint>

using namespace nvcuda;

#define TSTEPS 512
#define BATCH  128
#define HID    1024
#define NG     4096
#define NLAYER 2
#define NCTA_R 128
#define THR_TOT 320   // 8 consumer warps + 2 producer warps
#define N_CONS  256

// ---------------- device scratch ----------------
__device__ float  g_gatesT[(size_t)TSTEPS * NG * BATCH];          // [t][col][b]
__device__ __align__(16) __half g_hseq16[(size_t)TSTEPS * BATCH * HID];
__device__ __align__(16) __half g_h16[2][BATCH * HID];            // ping-pong h
__device__ __align__(16) __half g_x16[(size_t)TSTEPS * BATCH * HID];   // fp16 x
__device__ __align__(16) __half g_w16[(size_t)NLAYER * HID * NG];      // fp16 W_ih
__device__ unsigned int g_cnt[2];     // per-batch-group generation counters

// ---------------- recurrence smem layout (bytes) ----------------
#define SM_W     0
#define SM_A     147456
#define SM_ABUF  17408
#define SM_G     182272
#define SM_BIAS  217088
#define SM_TOTAL 217344

// ---------------- input-GEMM smem layout (bytes) ----------------
#define GI_A      0
#define GI_ABUF   10240
#define GI_B      30720
#define GI_BBUF   16896
#define GI_TOTAL  81408

__device__ __forceinline__ uint32_t smem_u32(const void* p) {
    uint32_t a;
    asm("{ .reg .u64 t; cvta.to.shared.u64 t, %1; cvt.u32.u64 %0, t; }" : "=r"(a) : "l"(p));
    return a;
}
__device__ __forceinline__ void cp16(uint32_t dst, const void* src) {
    asm volatile("cp.async.cg.shared.global [%0], [%1], 16;" :: "r"(dst), "l"(src));
}
#define CP_COMMIT() asm volatile("cp.async.commit_group;" ::: "memory")
#define CP_WAIT1()  asm volatile("cp.async.wait_group 1;" ::: "memory")
#define CP_WAIT0()  asm volatile("cp.async.wait_group 0;" ::: "memory")

#define BAR_SYNC(id, n)   asm volatile("bar.sync %0, %1;"   :: "r"(id), "r"(n) : "memory")
#define BAR_ARRIVE(id, n) asm volatile("bar.arrive %0, %1;" :: "r"(id), "r"(n) : "memory")

__device__ __forceinline__ void rel_add1(unsigned int* p) {
    asm volatile("red.release.gpu.global.add.u32 [%0], 1;" :: "l"(p) : "memory");
}
__device__ __forceinline__ unsigned int acq_ld(const unsigned int* p) {
    unsigned int v;
    asm volatile("ld.acquire.gpu.global.u32 %0, [%1];" : "=r"(v) : "l"(p) : "memory");
    return v;
}

__device__ __forceinline__ float sigf(float x) { return 1.f / (1.f + __expf(-x)); }
__device__ __forceinline__ uint32_t packh2(float a, float b) {
    return (uint32_t)__half_as_ushort(__float2half_rn(a)) |
           ((uint32_t)__half_as_ushort(__float2half_rn(b)) << 16);
}

// =================================================================================
// fp32 -> fp16 conversion (x and W_ih, once)
// =================================================================================
__global__ void cvt_f32_f16(const float* __restrict__ src, __half* __restrict__ dst)
{
    const size_t i = ((size_t)blockIdx.x * blockDim.x + threadIdx.x) * 4;
    const float4 v = *(const float4*)(src + i);
    *(uint2*)(dst + i) = make_uint2(packh2(v.x, v.y), packh2(v.z, v.w));
}

__global__ void init_cnt()
{
    if (threadIdx.x < 2) g_cnt[threadIdx.x] = 0u;
}

// =================================================================================
// Input GEMM fp16 (unchanged from round 13)
// =================================================================================
__global__ void __launch_bounds__(256, 1) gemm_input_f16(
    const __half* __restrict__ A,      // [T*B, 1024] fp16
    const __half* __restrict__ W,      // [1024, 4096] fp16
    float* __restrict__ CT)            // [T][col][b]
{
    extern __shared__ __align__(16) char smem[];
    const uint32_t sbase = smem_u32(smem);

    const int tid  = threadIdx.x;
    const int warp = tid >> 5;
    const int wm = warp >> 2;
    const int wn = warp & 3;
    const int bm = blockIdx.y;
    const int bn = blockIdx.x;

    const int a_row = tid >> 1, a_c8 = (tid & 1) * 16;
    const int b_row = tid >> 3, b_c8 = (tid & 7) * 32;

    const __half* Ag = A + (size_t)(bm * 128 + a_row) * HID;
    const __half* Wg = W + (size_t)b_row * NG + bn * 256;

    wmma::fragment<wmma::accumulator, 16, 16, 16, float> acc[4][4];
#pragma unroll
    for (int i = 0; i < 4; i++)
#pragma unroll
        for (int j = 0; j < 4; j++) wmma::fill_fragment(acc[i][j], 0.f);

#pragma unroll
    for (int c = 0; c < 2; ++c) {
        const uint32_t abase = sbase + GI_A + c * GI_ABUF;
        const uint32_t bbase = sbase + GI_B + c * GI_BBUF;
#pragma unroll
        for (int u = 0; u < 2; u++)
            cp16(abase + (uint32_t)(a_row * 40 + a_c8 + u * 8) * 2,
                 Ag + c * 32 + a_c8 + u * 8);
#pragma unroll
        for (int u = 0; u < 4; u++)
            cp16(bbase + (uint32_t)(b_row * 264 + b_c8 + u * 8) * 2,
                 Wg + (size_t)(c * 32) * NG + b_c8 + u * 8);
        CP_COMMIT();
    }

#pragma unroll 1
    for (int cc = 0; cc < 32; ++cc) {
        if (cc < 31) CP_WAIT1(); else CP_WAIT0();
        __syncthreads();

        if (cc < 30) {
            const int cn = cc + 2;
            const uint32_t abase = sbase + GI_A + (cn % 3) * GI_ABUF;
            const uint32_t bbase = sbase + GI_B + (cn % 3) * GI_BBUF;
#pragma unroll
            for (int u = 0; u < 2; u++)
                cp16(abase + (uint32_t)(a_row * 40 + a_c8 + u * 8) * 2,
                     Ag + cn * 32 + a_c8 + u * 8);
#pragma unroll
            for (int u = 0; u < 4; u++)
                cp16(bbase + (uint32_t)(b_row * 264 + b_c8 + u * 8) * 2,
                     Wg + (size_t)(cn * 32) * NG + b_c8 + u * 8);
            CP_COMMIT();
        }

        const __half* As = (const __half*)(smem + GI_A + (cc % 3) * GI_ABUF);
        const __half* Bs = (const __half*)(smem + GI_B + (cc % 3) * GI_BBUF);
#pragma unroll
        for (int kk = 0; kk < 32; kk += 16) {
            wmma::fragment<wmma::matrix_a, 16, 16, 16, __half, wmma::row_major> fa[4];
            wmma::fragment<wmma::matrix_b, 16, 16, 16, __half, wmma::row_major> fb[4];
#pragma unroll
            for (int i = 0; i < 4; i++)
                wmma::load_matrix_sync(fa[i], As + (size_t)(wm * 64 + i * 16) * 40 + kk, 40);
#pragma unroll
            for (int j = 0; j < 4; j++)
                wmma::load_matrix_sync(fb[j], Bs + (size_t)kk * 264 + wn * 64 + j * 16, 264);
#pragma unroll
            for (int i = 0; i < 4; i++)
#pragma unroll
                for (int j = 0; j < 4; j++)
                    wmma::mma_sync(acc[i][j], fa[i], fb[j], acc[i][j]);
        }
    }

    float* base = CT + (size_t)bm * NG * 128;
#pragma unroll
    for (int i = 0; i < 4; i++)
#pragma unroll
        for (int j = 0; j < 4; j++) {
            const int col = bn * 256 + wn * 64 + j * 16;
            const int row = wm * 64 + i * 16;
            wmma::store_matrix_sync(base + (size_t)col * 128 + row, acc[i][j],
                                    128, wmma::mem_col_major);
        }
}

// =================================================================================
// Persistent recurrence: R13 structure (batch-split + warp-specialized, one
// generation counter wait per step) with:
//  - per-bg counters (convergence set 64, monotonic across layers via epoch)
//  - single-spinner poll + producer-barrier broadcast (64x less L2 spin traffic)
//  - t=0 GEMM skipped (h0 == 0), producers start at t=1, no h-zero init needed
// =================================================================================
__global__ void __launch_bounds__(THR_TOT, 1) lstm_recur(
    const float* __restrict__ Whh,      // [HID, NG]
    const float* __restrict__ gatesT,   // [T][col][b]
    const float* __restrict__ b1, const float* __restrict__ b2,
    __half* __restrict__ seq16,         // layer-0 output (or null)
    float*  __restrict__ seq32,         // last-layer output (or null)
    float* __restrict__ hT, float* __restrict__ cT,
    unsigned epoch)                     // l * TSTEPS
{
    extern __shared__ __align__(16) char smem[];
    __half* Ws   = (__half*)(smem + SM_W);       // [1024][72]
    float*  Gs0  = (float*) (smem + SM_G);       // [64][68]
    float*  Gs1  = Gs0 + 64 * 68;
    float*  bias = (float*) (smem + SM_BIAS);    // [64]
    const uint32_t sbase = smem_u32(smem);

    const int tid = threadIdx.x;
    const int bx  = blockIdx.x;
    const int jg  = bx & 63;            // j-group: hidden cols [jg*16, jg*16+16)
    const int bg  = bx >> 6;            // batch group: rows [bg*64, bg*64+64)
    const int j0  = jg * 16;
    const int m0  = bg * 64;

    for (int idx = tid; idx < 1024 * 64; idx += THR_TOT) {
        const int k = idx >> 6, n = idx & 63;
        const int gate = n & 3, jl = n >> 2;
        Ws[k * 72 + n] = __float2half_rn(Whh[(size_t)k * NG + gate * HID + j0 + jl]);
    }
    if (tid < 64) {
        const int gate = tid & 3, jl = tid >> 2;
        bias[tid] = b1[gate * HID + j0 + jl] + b2[gate * HID + j0 + jl];
    }
    __syncthreads();

    if (tid >= N_CONS) {
        // =========================== PRODUCER WARPS ===========================
        const int ptid = tid - N_CONS;   // 0..63
        unsigned int* cnt = &g_cnt[bg];
#pragma unroll 1
        for (int t = 1; t < TSTEPS; ++t) {
            // wait for h_t: consumers' cumulative arrivals reach (epoch+t)*64
            const unsigned tgt = (epoch + (unsigned)t) * 64u;
            if (ptid == 0) { while (acq_ld(cnt) < tgt) { } }
            BAR_SYNC(8, 64);            // broadcast to other producer threads
            acq_ld(cnt);                // per-thread acquire (single, passes)

            const __half* hin = g_h16[t & 1] + (size_t)m0 * HID;
#pragma unroll 1
            for (int cc = 0; cc < 8; ++cc) {
                const int gp = (t - 1) * 8 + cc;
                const int slot = cc & 1;
                if (gp >= 2) BAR_SYNC(3 + slot, THR_TOT);   // wait slot empty
                const uint32_t dbase = sbase + SM_A + slot * SM_ABUF;
                const __half* hp = hin + cc * 128;
#pragma unroll
                for (int u = 0; u < 16; u++) {
                    const int idx = u * 64 + ptid;
                    const int row = idx >> 4, k8 = (idx & 15) * 8;
                    cp16(dbase + (uint32_t)(row * 136 + k8) * 2,
                         hp + (size_t)row * HID + k8);
                }
                CP_COMMIT();
                if (cc >= 1) {
                    CP_WAIT1();
                    BAR_ARRIVE(1 + ((cc - 1) & 1), THR_TOT);
                }
            }
            CP_WAIT0();
            BAR_ARRIVE(2, THR_TOT);                         // FULL chunk 7 (slot 1)
        }
        return;
    }

    // ============================ CONSUMER WARPS ============================
    const int wid   = tid >> 5;
    const int mhalf = wid & 1;
    const int nposw = (wid >> 1) & 1;
    const int khalf = wid >> 2;

    const int m    = tid & 63;
    const int jgrp = tid >> 6;
    float c4[4];
#pragma unroll
    for (int q = 0; q < 4; q++) c4[q] = 0.f;

    float gt[16];
    {
        const float* gb = gatesT + (m0 + m);
#pragma unroll
        for (int q = 0; q < 4; q++)
#pragma unroll
            for (int g = 0; g < 4; g++)
                gt[q * 4 + g] = gb[(size_t)(g * HID + j0 + jgrp * 4 + q) * BATCH];
    }

#pragma unroll 1
    for (int t = 0; t < TSTEPS; ++t) {
        __half* hout = g_h16[(t + 1) & 1];

        wmma::fragment<wmma::accumulator, 16, 16, 16, float> acc[2][2];
#pragma unroll
        for (int i = 0; i < 2; i++)
#pragma unroll
            for (int j = 0; j < 2; j++) wmma::fill_fragment(acc[i][j], 0.f);

        if (t > 0) {   // t=0: h0 == 0, recurrent term vanishes — skip GEMM
#pragma unroll 1
            for (int cc = 0; cc < 8; ++cc) {
                const int slot = cc & 1;
                BAR_SYNC(1 + slot, THR_TOT);    // wait slot full

                const __half* Ap = (const __half*)(smem + SM_A + slot * SM_ABUF)
                                 + (size_t)mhalf * 32 * 136 + khalf * 64;
                const __half* Wp = Ws + (size_t)(cc * 128 + khalf * 64) * 72 + nposw * 32;
#pragma unroll
                for (int kk = 0; kk < 64; kk += 16) {
                    wmma::fragment<wmma::matrix_a, 16, 16, 16, __half, wmma::row_major> fa[2];
                    wmma::fragment<wmma::matrix_b, 16, 16, 16, __half, wmma::row_major> fb[2];
#pragma unroll
                    for (int i = 0; i < 2; i++)
                        wmma::load_matrix_sync(fa[i], Ap + (size_t)(i * 16) * 136 + kk, 136);
#pragma unroll
                    for (int j = 0; j < 2; j++)
                        wmma::load_matrix_sync(fb[j], Wp + (size_t)kk * 72 + j * 16, 72);
#pragma unroll
                    for (int i = 0; i < 2; i++)
#pragma unroll
                        for (int j = 0; j < 2; j++)
                            wmma::mma_sync(acc[i][j], fa[i], fb[j], acc[i][j]);
                }
                BAR_ARRIVE(3 + slot, THR_TOT);  // slot consumed
            }
        }

        float* Gsw = khalf ? Gs1 : Gs0;
#pragma unroll
        for (int i = 0; i < 2; i++)
#pragma unroll
            for (int j = 0; j < 2; j++)
                wmma::store_matrix_sync(Gsw + (size_t)(mhalf * 32 + i * 16) * 68
                                             + nposw * 32 + j * 16,
                                        acc[i][j], 68, wmma::mem_row_major);
        BAR_SYNC(9, N_CONS);

        float hn[4];
#pragma unroll
        for (int q = 0; q < 4; q++) {
            const int n = jgrp * 16 + q * 4;
            const float4 v0 = *(const float4*)(Gs0 + (size_t)m * 68 + n);
            const float4 v1 = *(const float4*)(Gs1 + (size_t)m * 68 + n);
            const float zi = v0.x + v1.x + gt[q * 4 + 0] + bias[n + 0];
            const float zf = v0.y + v1.y + gt[q * 4 + 1] + bias[n + 1];
            const float zg = v0.z + v1.z + gt[q * 4 + 2] + bias[n + 2];
            const float zo = v0.w + v1.w + gt[q * 4 + 3] + bias[n + 3];
            const float cn = sigf(zf) * c4[q] + sigf(zi) * tanhf(zg);
            hn[q] = sigf(zo) * tanhf(cn);
            c4[q] = cn;
        }

        const size_t ob = (size_t)(m0 + m) * HID + j0 + jgrp * 4;
        const uint2 upk = make_uint2(packh2(hn[0], hn[1]), packh2(hn[2], hn[3]));
        *(uint2*)(hout + ob) = upk;

        BAR_SYNC(9, N_CONS);               // all consumer hout stores done
        if (tid == 0) rel_add1(&g_cnt[bg]);

        // ---- work shadow ----
        if (seq16) *(uint2*)(seq16 + (size_t)t * BATCH * HID + ob) = upk;
        if (seq32)
            *(float4*)(seq32 + (size_t)t * BATCH * HID + ob) =
                make_float4(hn[0], hn[1], hn[2], hn[3]);
        if (t == TSTEPS - 1) {
            *(float4*)(hT + ob) = make_float4(hn[0], hn[1], hn[2], hn[3]);
            *(float4*)(cT + ob) = make_float4(c4[0], c4[1], c4[2], c4[3]);
        }
        if (t + 1 < TSTEPS) {
            const float* gb = gatesT + (size_t)(t + 1) * NG * BATCH + (m0 + m);
#pragma unroll
            for (int q = 0; q < 4; q++)
#pragma unroll
                for (int g = 0; g < 4; g++)
                    gt[q * 4 + g] = gb[(size_t)(g * HID + j0 + jgrp * 4 + q) * BATCH];
        }
    }
}

// =================================================================================
extern "C" void kernel_launch(void* const* d_in, const int* in_sizes, int n_in,
                              void* d_out, int out_size)
{
    const float* x   = (const float*)d_in[0];
    const float* wih = (const float*)d_in[1];
    const float* whh = (const float*)d_in[2];
    const float* bih = (const float*)d_in[3];
    const float* bhh = (const float*)d_in[4];
    float* out = (float*)d_out;

    cudaFuncSetAttribute(lstm_recur, cudaFuncAttributeMaxDynamicSharedMemorySize, SM_TOTAL);
    cudaFuncSetAttribute(gemm_input_f16, cudaFuncAttributeMaxDynamicSharedMemorySize, GI_TOTAL);

    float  *gatesT;
    __half *hseq16, *x16, *w16;
    cudaGetSymbolAddress((void**)&gatesT, g_gatesT);
    cudaGetSymbolAddress((void**)&hseq16, g_hseq16);
    cudaGetSymbolAddress((void**)&x16,    g_x16);
    cudaGetSymbolAddress((void**)&w16,    g_w16);

    float* hT_base = out + (size_t)TSTEPS * BATCH * HID;
    float* cT_base = hT_base + (size_t)NLAYER * BATCH * HID;

    cvt_f32_f16<<<(TSTEPS * BATCH * HID) / 1024, 256>>>(x, x16);
    cvt_f32_f16<<<(NLAYER * HID * NG) / 1024, 256>>>(wih, w16);
    init_cnt<<<1, 32>>>();

    for (int l = 0; l < NLAYER; ++l) {
        const __half* A16 = l ? hseq16 : x16;
        const __half* W16 = w16 + (size_t)l * HID * NG;
        const float* Whh = whh + (size_t)l * HID * NG;
        const float* B1  = bih + (size_t)l * NG;
        const float* B2  = bhh + (size_t)l * NG;
        float* hT = hT_base + (size_t)l * BATCH * HID;
        float* cT = cT_base + (size_t)l * BATCH * HID;

        gemm_input_f16<<<dim3(NG / 256, TSTEPS), 256, GI_TOTAL>>>(A16, W16, gatesT);

        lstm_recur<<<NCTA_R, THR_TOT, SM_TOTAL>>>(
            Whh, gatesT, B1, B2,
            (l == 0) ? hseq16 : (__half*)nullptr,
            (l == 1) ? out    : (float*)nullptr,
            hT, cT,
            (unsigned)(l * TSTEPS));
    }
}